// round 6
// baseline (speedup 1.0000x reference)
#include <cuda_runtime.h>

#define HH 512
#define WW 512
#define BATCH 16
#define RPB 4          // output rows per block (2 thread-rows x 2 rows each)
#define PXT 8          // pixels per thread along x (per row)
#define TX 64
#define TYW 2          // threadIdx.y range; each thread does 2 rows
#define NTHREADS (TX * TYW)   // 128
#define TILE_W 516
#define TILE_STRIDE 520
#define TILE_H (RPB + 4)      // 8

__device__ __forceinline__ void ce(float& a, float& b) {
    float t = fminf(a, b);
    b = fmaxf(a, b);
    a = t;
}

// non-destructive insert of x into sorted m[4] -> sorted r[5]
__device__ __forceinline__ void insert5(const float m[4], float x, float r[5]) {
    r[0] = fminf(x, m[0]); float c = fmaxf(x, m[0]);
    r[1] = fminf(c, m[1]); c = fmaxf(c, m[1]);
    r[2] = fminf(c, m[2]); c = fmaxf(c, m[2]);
    r[3] = fminf(c, m[3]); r[4] = fmaxf(c, m[3]);
}

// From 6 vertical samples v[0..5] build sorted columns A (rows 0..4) and
// B (rows 1..5), plus sums/sumsq/centers for both.
__device__ __forceinline__ void colpair(const float v[6], float A[5], float B[5],
                                        float& sA, float& qA, float& sB, float& qB,
                                        float& cenA, float& cenB) {
    float t  = (v[1] + v[2]) + (v[3] + v[4]);
    sA = v[0] + t;
    sB = t + v[5];
    float qt = fmaf(v[1], v[1], fmaf(v[2], v[2], fmaf(v[3], v[3], v[4] * v[4])));
    qA = fmaf(v[0], v[0], qt);
    qB = fmaf(v[5], v[5], qt);
    cenA = v[2];
    cenB = v[3];
    float m[4] = {v[1], v[2], v[3], v[4]};
    ce(m[0], m[1]); ce(m[2], m[3]); ce(m[0], m[2]); ce(m[1], m[3]); ce(m[1], m[2]);
    insert5(m, v[0], A);
    insert5(m, v[5], B);
}

// Batcher odd-even merge of two sorted 5-lists -> sorted 10-list (13 CE)
__device__ __forceinline__ void merge55(const float x[5], const float y[5], float z[10]) {
    float t0 = fminf(x[0], y[0]), t1 = fmaxf(x[0], y[0]);
    float w0 = fminf(x[4], y[4]), w1 = fmaxf(x[4], y[4]);
    float r1 = fminf(w0, t1),     r2 = fmaxf(w0, t1);
    float s0 = fminf(x[2], y[2]), s1 = fmaxf(x[2], y[2]);
    float p0 = t0;
    float p1 = fminf(s0, r1), p2 = fmaxf(s0, r1);
    float p3 = fminf(s1, r2), p4 = fmaxf(s1, r2);
    float p5 = w1;
    float a0 = fminf(x[1], y[1]), a1 = fmaxf(x[1], y[1]);
    float b0 = fminf(x[3], y[3]), b1 = fmaxf(x[3], y[3]);
    float q0 = a0;
    float q1 = fminf(b0, a1), q2 = fmaxf(b0, a1);
    float q3 = b1;
    z[0] = p0;
    z[1] = fminf(q0, p1); z[2] = fmaxf(q0, p1);
    z[3] = fminf(q1, p2); z[4] = fmaxf(q1, p2);
    z[5] = fminf(q2, p3); z[6] = fmaxf(q2, p3);
    z[7] = fminf(q3, p4); z[8] = fmaxf(q3, p4);
    z[9] = p5;
}

// Pruned OEM(10,10): ranks 7..12 (s[0]=s7 ... s[5]=s12) of the merged 20-list.
__device__ __forceinline__ void prune_mid(const float m1[10], const float m2[10], float s[6]) {
    float t1  = fmaxf(m1[0], m2[0]);
    float w0  = fminf(m1[8], m2[8]);
    float r1  = fminf(w0, t1),  r2 = fmaxf(w0, t1);
    float s0  = fminf(m1[4], m2[4]), s1 = fmaxf(m1[4], m2[4]);
    float p2  = fmaxf(s0, r1),  p3 = fminf(s1, r2);
    float t1q = fmaxf(m1[2], m2[2]);
    float w0q = fminf(m1[6], m2[6]);
    float q1  = fminf(w0q, t1q), q2 = fmaxf(w0q, t1q);
    float d4  = fmaxf(q1, p2);
    float d5  = fminf(q2, p3), d6 = fmaxf(q2, p3);

    float t1g = fmaxf(m1[1], m2[1]);
    float w0g = fminf(m1[9], m2[9]);
    float r1g = fminf(w0g, t1g), r2g = fmaxf(w0g, t1g);
    float s0g = fminf(m1[5], m2[5]), s1g = fmaxf(m1[5], m2[5]);
    float p2g = fmaxf(s0g, r1g), p3g = fminf(s1g, r2g);
    float t1h = fmaxf(m1[3], m2[3]);
    float w0h = fminf(m1[7], m2[7]);
    float q1g = fminf(w0h, t1h), q2g = fmaxf(w0h, t1h);
    float g3  = fminf(q1g, p2g), g4 = fmaxf(q1g, p2g);
    float g5  = fminf(q2g, p3g);

    s[0] = fminf(g3, d4); s[1] = fmaxf(g3, d4);
    s[2] = fminf(g4, d5); s[3] = fmaxf(g4, d5);
    s[4] = fminf(g5, d6); s[5] = fmaxf(g5, d6);
}

// 13th smallest of S(20) U E(5), tree-shaped.
__device__ __forceinline__ float sel13(const float s[6], const float E[5]) {
    float a = fmaxf(s[4], E[0]);
    float b = fmaxf(s[3], E[1]);
    float c = fmaxf(s[2], E[2]);
    float d = fmaxf(s[1], E[3]);
    float e = fmaxf(s[0], E[4]);
    return fminf(fminf(fminf(a, b), fminf(c, d)), fminf(e, s[5]));
}

__device__ __forceinline__ float sum5(const float v[5]) {
    return ((v[0] + v[1]) + (v[2] + v[3])) + v[4];
}
__device__ __forceinline__ float sq5(const float v[5]) {
    return fmaf(v[0], v[0], fmaf(v[1], v[1], fmaf(v[2], v[2], fmaf(v[3], v[3], v[4] * v[4]))));
}

__global__ __launch_bounds__(NTHREADS, 4)
void Net_29291676958726_kernel(const float* __restrict__ x,
                               const float* __restrict__ noise_var,
                               const float* __restrict__ noise_bias,
                               float* __restrict__ out) {
    __shared__ float tile[TILE_H][TILE_STRIDE];

    const int b   = blockIdx.y;
    const int rb  = blockIdx.x * RPB;
    const int tid = threadIdx.y * TX + threadIdx.x;
    const float* __restrict__ xb_ptr = x + (size_t)b * HH * WW;

    // zero-padded tile load: 8 rows x 516 cols, striped over 128 threads
#pragma unroll
    for (int r = 0; r < TILE_H; r++) {
        const int gr = rb - 2 + r;
        const bool rok = (unsigned)gr < HH;
        const float* __restrict__ src = xb_ptr + (size_t)gr * WW;
#pragma unroll
        for (int cc = 0; cc < 5; cc++) {
            int c = tid + cc * NTHREADS;
            if (c < TILE_W) {
                int gc = c - 2;
                tile[r][c] = (rok && (unsigned)gc < WW) ? src[gc] : 0.0f;
            }
        }
    }
    __syncthreads();

    const float nv = noise_var[0];
    const float nb = noise_bias[0];

    const int ry    = 2 * threadIdx.y;      // tile-relative top pixel row of this thread
    const int xbase = threadIdx.x * PXT;

    // Two independent row pipelines (rp=0 -> pixel row ry, rp=1 -> ry+1)
    float Ecur[2][5], Enext[2][5], C3[2][5];
    float M[2][10];
    float sM[2], qM[2], s3[2], q3[2], cenE[2], cenO[2];

    // ---- prologue: columns 0..3 for both rows ----
    {
        float c0[2][5], c1[2][5], c2[2][5], c3v[2][5];
        float sA[2][4], qA[2][4], cn[2][4];
#pragma unroll
        for (int jp = 0; jp < 2; jp++) {
            float2 gg[6];
#pragma unroll
            for (int k = 0; k < 6; k++)
                gg[k] = *(const float2*)&tile[ry + k][xbase + 2 * jp];
            // column 2*jp (x component)
            {
                float v[6];
#pragma unroll
                for (int k = 0; k < 6; k++) v[k] = gg[k].x;
                float* A = (jp ? c2[0] : c0[0]);
                float* B = (jp ? c2[1] : c0[1]);
                colpair(v, A, B, sA[0][2 * jp], qA[0][2 * jp], sA[1][2 * jp], qA[1][2 * jp],
                        cn[0][2 * jp], cn[1][2 * jp]);
            }
            // column 2*jp+1 (y component)
            {
                float v[6];
#pragma unroll
                for (int k = 0; k < 6; k++) v[k] = gg[k].y;
                float* A = (jp ? c3v[0] : c1[0]);
                float* B = (jp ? c3v[1] : c1[1]);
                colpair(v, A, B, sA[0][2 * jp + 1], qA[0][2 * jp + 1], sA[1][2 * jp + 1], qA[1][2 * jp + 1],
                        cn[0][2 * jp + 1], cn[1][2 * jp + 1]);
            }
        }
#pragma unroll
        for (int rp = 0; rp < 2; rp++) {
            sM[rp] = sA[rp][1] + sA[rp][2];
            qM[rp] = qA[rp][1] + qA[rp][2];
            s3[rp] = sA[rp][3];
            q3[rp] = qA[rp][3];
            cenE[rp] = cn[rp][2];
            cenO[rp] = cn[rp][3];
#pragma unroll
            for (int k = 0; k < 5; k++) {
                Ecur[rp][k]  = c0[rp][k];
                Enext[rp][k] = c2[rp][k];
                C3[rp][k]    = c3v[rp][k];
            }
            merge55(c1[rp], c2[rp], M[rp]);
        }
    }

    float2* __restrict__ orow0 =
        (float2*)(out + (size_t)b * HH * WW + (size_t)(rb + ry) * WW + xbase);
    float2* __restrict__ orow1 =
        (float2*)(out + (size_t)b * HH * WW + (size_t)(rb + ry + 1) * WW + xbase);

#pragma unroll
    for (int t = 0; t < PXT / 2; t++) {
        // fresh columns 2t+4, 2t+5 for both rows
        float v4[2][5], v5[2][5];
        float s4[2], q4[2], s5[2], q5[2], cen4[2], cen5[2];
        {
            float2 gg[6];
#pragma unroll
            for (int k = 0; k < 6; k++)
                gg[k] = *(const float2*)&tile[ry + k][xbase + 2 * t + 4];
            {
                float v[6];
#pragma unroll
                for (int k = 0; k < 6; k++) v[k] = gg[k].x;
                colpair(v, v4[0], v4[1], s4[0], q4[0], s4[1], q4[1], cen4[0], cen4[1]);
            }
            {
                float v[6];
#pragma unroll
                for (int k = 0; k < 6; k++) v[k] = gg[k].y;
                colpair(v, v5[0], v5[1], s5[0], q5[0], s5[1], q5[1], cen5[0], cen5[1]);
            }
        }

#pragma unroll
        for (int rp = 0; rp < 2; rp++) {
            float N[10];
            merge55(C3[rp], v4[rp], N);

            float s[6];
            prune_mid(M[rp], N, s);

            float sN = s3[rp] + s4[rp];
            float qN = q3[rp] + q4[rp];

            // even pixel
            float sE = sum5(Ecur[rp]), qE = sq5(Ecur[rp]);
            float sum_e = sE + sM[rp] + sN;
            float sq_e  = qE + qM[rp] + qN;
            float var_e = fmaxf((sq_e - sum_e * sum_e * 0.04f) * (1.0f / 24.0f), 0.0f);
            float med_e = sel13(s, Ecur[rp]);
            float ce_   = cenE[rp];
            float y_e   = ce_ - nv * __fdividef(ce_ - med_e + nb, var_e + 1e-10f);

            // odd pixel
            float sum_o = sM[rp] + sN + s5[rp];
            float sq_o  = qM[rp] + qN + q5[rp];
            float var_o = fmaxf((sq_o - sum_o * sum_o * 0.04f) * (1.0f / 24.0f), 0.0f);
            float med_o = sel13(s, v5[rp]);
            float co_   = cenO[rp];
            float y_o   = co_ - nv * __fdividef(co_ - med_o + nb, var_o + 1e-10f);

            float2 o2 = make_float2(fmaxf(y_e, 0.0f), fmaxf(y_o, 0.0f));
            if (rp == 0) orow0[t] = o2; else orow1[t] = o2;

            // rotate
#pragma unroll
            for (int k = 0; k < 5; k++) {
                Ecur[rp][k]  = Enext[rp][k];
                Enext[rp][k] = v4[rp][k];
                C3[rp][k]    = v5[rp][k];
            }
#pragma unroll
            for (int k = 0; k < 10; k++) M[rp][k] = N[k];
            sM[rp] = sN;      qM[rp] = qN;
            s3[rp] = s5[rp];  q3[rp] = q5[rp];
            cenE[rp] = cen4[rp];
            cenO[rp] = cen5[rp];
        }
    }
}

extern "C" void kernel_launch(void* const* d_in, const int* in_sizes, int n_in,
                              void* d_out, int out_size) {
    const float* x  = (const float*)d_in[0];
    const float* nv = (const float*)d_in[1];
    const float* nb = (const float*)d_in[2];
    float* out = (float*)d_out;

    dim3 block(TX, TYW);
    dim3 grid(HH / RPB, BATCH);
    Net_29291676958726_kernel<<<grid, block>>>(x, nv, nb, out);
}

// round 7
// speedup vs baseline: 1.0934x; 1.0934x over previous
#include <cuda_runtime.h>

#define HH 512
#define WW 512
#define BATCH 16
#define RPB 4        // rows per block
#define PXT 8        // pixels per thread along x
#define TX 64        // threads in x (TX*PXT = 512)
#define TILE_W 516   // 512 + 2 halo each side
#define TILE_STRIDE 520
#define TILE_H (RPB + 4)
#define NTHREADS (TX * RPB)

// XOR bank swizzle: fold byte-address bits [9:8] into bank bits [4:3].
// Preserves bits [2:0] (8B alignment / float2 contiguity) and stays within
// the same 32B block.
__device__ __forceinline__ int swz(int byte_off) {
    return byte_off ^ ((byte_off >> 5) & 0x18);
}

__device__ __forceinline__ void ce(float& a, float& b) {
    float t = fminf(a, b);
    b = fmaxf(a, b);
    a = t;
}

// optimal 9-CE sorting network for 5 elements
__device__ __forceinline__ void sort5(float v[5]) {
    ce(v[0], v[1]); ce(v[3], v[4]); ce(v[2], v[4]);
    ce(v[2], v[3]); ce(v[0], v[3]); ce(v[0], v[2]);
    ce(v[1], v[4]); ce(v[1], v[3]); ce(v[1], v[2]);
}

// Batcher odd-even merge of two sorted 5-lists -> sorted 10-list (13 CE)
__device__ __forceinline__ void merge55(const float x[5], const float y[5], float z[10]) {
    float t0 = fminf(x[0], y[0]), t1 = fmaxf(x[0], y[0]);
    float w0 = fminf(x[4], y[4]), w1 = fmaxf(x[4], y[4]);
    float r1 = fminf(w0, t1),     r2 = fmaxf(w0, t1);
    float s0 = fminf(x[2], y[2]), s1 = fmaxf(x[2], y[2]);
    float p0 = t0;
    float p1 = fminf(s0, r1), p2 = fmaxf(s0, r1);
    float p3 = fminf(s1, r2), p4 = fmaxf(s1, r2);
    float p5 = w1;
    float a0 = fminf(x[1], y[1]), a1 = fmaxf(x[1], y[1]);
    float b0 = fminf(x[3], y[3]), b1 = fmaxf(x[3], y[3]);
    float q0 = a0;
    float q1 = fminf(b0, a1), q2 = fmaxf(b0, a1);
    float q3 = b1;
    z[0] = p0;
    z[1] = fminf(q0, p1); z[2] = fmaxf(q0, p1);
    z[3] = fminf(q1, p2); z[4] = fmaxf(q1, p2);
    z[5] = fminf(q2, p3); z[6] = fmaxf(q2, p3);
    z[7] = fminf(q3, p4); z[8] = fmaxf(q3, p4);
    z[9] = p5;
}

// Pruned OEM(10,10): ranks 7..12 (s[0]=s7 ... s[5]=s12) of the merged 20-list.
__device__ __forceinline__ void prune_mid(const float m1[10], const float m2[10], float s[6]) {
    float t1  = fmaxf(m1[0], m2[0]);
    float w0  = fminf(m1[8], m2[8]);
    float r1  = fminf(w0, t1),  r2 = fmaxf(w0, t1);
    float s0  = fminf(m1[4], m2[4]), s1 = fmaxf(m1[4], m2[4]);
    float p2  = fmaxf(s0, r1),  p3 = fminf(s1, r2);
    float t1q = fmaxf(m1[2], m2[2]);
    float w0q = fminf(m1[6], m2[6]);
    float q1  = fminf(w0q, t1q), q2 = fmaxf(w0q, t1q);
    float d4  = fmaxf(q1, p2);
    float d5  = fminf(q2, p3), d6 = fmaxf(q2, p3);

    float t1g = fmaxf(m1[1], m2[1]);
    float w0g = fminf(m1[9], m2[9]);
    float r1g = fminf(w0g, t1g), r2g = fmaxf(w0g, t1g);
    float s0g = fminf(m1[5], m2[5]), s1g = fmaxf(m1[5], m2[5]);
    float p2g = fmaxf(s0g, r1g), p3g = fminf(s1g, r2g);
    float t1h = fmaxf(m1[3], m2[3]);
    float w0h = fminf(m1[7], m2[7]);
    float q1g = fminf(w0h, t1h), q2g = fmaxf(w0h, t1h);
    float g3  = fminf(q1g, p2g), g4 = fmaxf(q1g, p2g);
    float g5  = fminf(q2g, p3g);

    s[0] = fminf(g3, d4); s[1] = fmaxf(g3, d4);
    s[2] = fminf(g4, d5); s[3] = fmaxf(g4, d5);
    s[4] = fminf(g5, d6); s[5] = fmaxf(g5, d6);
}

// 13th smallest of S(20) U E(5), tree-shaped.
__device__ __forceinline__ float sel13(const float s[6], const float E[5]) {
    float a = fmaxf(s[4], E[0]);
    float b = fmaxf(s[3], E[1]);
    float c = fmaxf(s[2], E[2]);
    float d = fmaxf(s[1], E[3]);
    float e = fmaxf(s[0], E[4]);
    return fminf(fminf(fminf(a, b), fminf(c, d)), fminf(e, s[5]));
}

__device__ __forceinline__ float sum5(const float v[5]) {
    return ((v[0] + v[1]) + (v[2] + v[3])) + v[4];
}
__device__ __forceinline__ float sq5(const float v[5]) {
    return fmaf(v[0], v[0], fmaf(v[1], v[1], fmaf(v[2], v[2], fmaf(v[3], v[3], v[4] * v[4]))));
}

__global__ __launch_bounds__(NTHREADS, 4)
void Net_29291676958726_kernel(const float* __restrict__ x,
                               const float* __restrict__ noise_var,
                               const float* __restrict__ noise_bias,
                               float* __restrict__ out) {
    __shared__ float tilef[TILE_H * TILE_STRIDE];
    char* __restrict__ tb = (char*)tilef;

    const int b   = blockIdx.y;
    const int rb  = blockIdx.x * RPB;
    const int tid = threadIdx.y * TX + threadIdx.x;
    const float* __restrict__ xb_ptr = x + (size_t)b * HH * WW;

    // zero-padded tile load with swizzled stores
#pragma unroll
    for (int r = 0; r < TILE_H; r++) {
        const int gr = rb - 2 + r;
        const bool rok = (unsigned)gr < HH;
        const float* __restrict__ src = xb_ptr + (size_t)gr * WW;
        const int rowoff = r * (TILE_STRIDE * 4);
#pragma unroll
        for (int cc = 0; cc < 3; cc++) {
            int c = tid + cc * NTHREADS;
            if (c < TILE_W) {
                int gc = c - 2;
                float v = (rok && (unsigned)gc < WW) ? src[gc] : 0.0f;
                *(float*)(tb + swz(rowoff + c * 4)) = v;
            }
        }
    }
    __syncthreads();

    const float nv = noise_var[0];
    const float nb = noise_bias[0];

    const int ty    = threadIdx.y;
    const int xbase = threadIdx.x * PXT;
    const int base_off = ty * (TILE_STRIDE * 4) + xbase * 4;

    // Rotating live state
    float Ecur[5], Enext[5], C3[5];
    float M[10];
    float sM, qM, s3, q3, cenE, cenO;

    // ---- prologue: columns 0..3 ----
    {
        float c0[5], c1[5], c2[5], c3v[5];
#pragma unroll
        for (int jp = 0; jp < 2; jp++) {
#pragma unroll
            for (int k = 0; k < 5; k++) {
                float2 gg = *(const float2*)(tb + swz(base_off + k * (TILE_STRIDE * 4) + jp * 8));
                (jp ? c2 : c0)[k]  = gg.x;
                (jp ? c3v : c1)[k] = gg.y;
            }
        }
        sM   = sum5(c1) + sum5(c2);
        qM   = sq5(c1) + sq5(c2);
        s3   = sum5(c3v);
        q3   = sq5(c3v);
        cenE = c2[2];
        cenO = c3v[2];
        sort5(c0); sort5(c1); sort5(c2); sort5(c3v);
#pragma unroll
        for (int k = 0; k < 5; k++) { Ecur[k] = c0[k]; Enext[k] = c2[k]; C3[k] = c3v[k]; }
        merge55(c1, c2, M);
    }

    float2* __restrict__ orow =
        (float2*)(out + (size_t)b * HH * WW + (size_t)(rb + ty) * WW + xbase);

#pragma unroll
    for (int t = 0; t < PXT / 2; t++) {
        // fresh columns 2t+4, 2t+5 (swizzled float2 loads)
        float v4[5], v5[5];
#pragma unroll
        for (int k = 0; k < 5; k++) {
            float2 gg = *(const float2*)(tb + swz(base_off + k * (TILE_STRIDE * 4) + (2 * t + 4) * 4));
            v4[k] = gg.x;
            v5[k] = gg.y;
        }
        float s4 = sum5(v4), q4 = sq5(v4);
        float s5 = sum5(v5), q5 = sq5(v5);
        float cen4 = v4[2], cen5 = v5[2];
        sort5(v4); sort5(v5);

        float N[10];                   // merge(col 2t+3, col 2t+4) = next M
        merge55(C3, v4, N);

        float s[6];
        prune_mid(M, N, s);

        float sN = s3 + s4;
        float qN = q3 + q4;

        // even pixel p = 2t
        float sE = sum5(Ecur), qE = sq5(Ecur);
        float sum_e = sE + sM + sN;
        float sq_e  = qE + qM + qN;
        float var_e = fmaxf((sq_e - sum_e * sum_e * 0.04f) * (1.0f / 24.0f), 0.0f);
        float med_e = sel13(s, Ecur);
        float y_e   = cenE - nv * __fdividef(cenE - med_e + nb, var_e + 1e-10f);

        // odd pixel p = 2t+1
        float sum_o = sM + sN + s5;
        float sq_o  = qM + qN + q5;
        float var_o = fmaxf((sq_o - sum_o * sum_o * 0.04f) * (1.0f / 24.0f), 0.0f);
        float med_o = sel13(s, v5);
        float y_o   = cenO - nv * __fdividef(cenO - med_o + nb, var_o + 1e-10f);

        orow[t] = make_float2(fmaxf(y_e, 0.0f), fmaxf(y_o, 0.0f));

        // rotate state for pair t+1
#pragma unroll
        for (int k = 0; k < 5; k++) { Ecur[k] = Enext[k]; Enext[k] = v4[k]; C3[k] = v5[k]; }
#pragma unroll
        for (int k = 0; k < 10; k++) M[k] = N[k];
        sM = sN; qM = qN;
        s3 = s5; q3 = q5;
        cenE = cen4; cenO = cen5;
    }
}

extern "C" void kernel_launch(void* const* d_in, const int* in_sizes, int n_in,
                              void* d_out, int out_size) {
    const float* x  = (const float*)d_in[0];
    const float* nv = (const float*)d_in[1];
    const float* nb = (const float*)d_in[2];
    float* out = (float*)d_out;

    dim3 block(TX, RPB);
    dim3 grid(HH / RPB, BATCH);
    Net_29291676958726_kernel<<<grid, block>>>(x, nv, nb, out);
}

// round 8
// speedup vs baseline: 1.1867x; 1.0853x over previous
#include <cuda_runtime.h>

#define HH 512
#define WW 512
#define BATCH 16
#define RPB 8        // rows per block (= threadIdx.y range)
#define PXT 16       // pixels per thread along x
#define TX 32        // threads in x (TX*PXT = 512)
#define TILE_W 516   // 512 + 2 halo each side
#define TILE_STRIDE 520
#define TILE_H (RPB + 4)      // 12
#define NTHREADS (TX * RPB)   // 256

__device__ __forceinline__ void ce(float& a, float& b) {
    float t = fminf(a, b);
    b = fmaxf(a, b);
    a = t;
}

// optimal 9-CE sorting network for 5 elements
__device__ __forceinline__ void sort5(float v[5]) {
    ce(v[0], v[1]); ce(v[3], v[4]); ce(v[2], v[4]);
    ce(v[2], v[3]); ce(v[0], v[3]); ce(v[0], v[2]);
    ce(v[1], v[4]); ce(v[1], v[3]); ce(v[1], v[2]);
}

// Batcher odd-even merge of two sorted 5-lists -> sorted 10-list (13 CE)
__device__ __forceinline__ void merge55(const float x[5], const float y[5], float z[10]) {
    float t0 = fminf(x[0], y[0]), t1 = fmaxf(x[0], y[0]);
    float w0 = fminf(x[4], y[4]), w1 = fmaxf(x[4], y[4]);
    float r1 = fminf(w0, t1),     r2 = fmaxf(w0, t1);
    float s0 = fminf(x[2], y[2]), s1 = fmaxf(x[2], y[2]);
    float p0 = t0;
    float p1 = fminf(s0, r1), p2 = fmaxf(s0, r1);
    float p3 = fminf(s1, r2), p4 = fmaxf(s1, r2);
    float p5 = w1;
    float a0 = fminf(x[1], y[1]), a1 = fmaxf(x[1], y[1]);
    float b0 = fminf(x[3], y[3]), b1 = fmaxf(x[3], y[3]);
    float q0 = a0;
    float q1 = fminf(b0, a1), q2 = fmaxf(b0, a1);
    float q3 = b1;
    z[0] = p0;
    z[1] = fminf(q0, p1); z[2] = fmaxf(q0, p1);
    z[3] = fminf(q1, p2); z[4] = fmaxf(q1, p2);
    z[5] = fminf(q2, p3); z[6] = fmaxf(q2, p3);
    z[7] = fminf(q3, p4); z[8] = fmaxf(q3, p4);
    z[9] = p5;
}

// Pruned OEM(10,10): ranks 7..12 (s[0]=s7 ... s[5]=s12) of the merged 20-list.
__device__ __forceinline__ void prune_mid(const float m1[10], const float m2[10], float s[6]) {
    float t1  = fmaxf(m1[0], m2[0]);
    float w0  = fminf(m1[8], m2[8]);
    float r1  = fminf(w0, t1),  r2 = fmaxf(w0, t1);
    float s0  = fminf(m1[4], m2[4]), s1 = fmaxf(m1[4], m2[4]);
    float p2  = fmaxf(s0, r1),  p3 = fminf(s1, r2);
    float t1q = fmaxf(m1[2], m2[2]);
    float w0q = fminf(m1[6], m2[6]);
    float q1  = fminf(w0q, t1q), q2 = fmaxf(w0q, t1q);
    float d4  = fmaxf(q1, p2);
    float d5  = fminf(q2, p3), d6 = fmaxf(q2, p3);

    float t1g = fmaxf(m1[1], m2[1]);
    float w0g = fminf(m1[9], m2[9]);
    float r1g = fminf(w0g, t1g), r2g = fmaxf(w0g, t1g);
    float s0g = fminf(m1[5], m2[5]), s1g = fmaxf(m1[5], m2[5]);
    float p2g = fmaxf(s0g, r1g), p3g = fminf(s1g, r2g);
    float t1h = fmaxf(m1[3], m2[3]);
    float w0h = fminf(m1[7], m2[7]);
    float q1g = fminf(w0h, t1h), q2g = fmaxf(w0h, t1h);
    float g3  = fminf(q1g, p2g), g4 = fmaxf(q1g, p2g);
    float g5  = fminf(q2g, p3g);

    s[0] = fminf(g3, d4); s[1] = fmaxf(g3, d4);
    s[2] = fminf(g4, d5); s[3] = fmaxf(g4, d5);
    s[4] = fminf(g5, d6); s[5] = fmaxf(g5, d6);
}

// 13th smallest of S(20) U E(5), tree-shaped.
__device__ __forceinline__ float sel13(const float s[6], const float E[5]) {
    float a = fmaxf(s[4], E[0]);
    float b = fmaxf(s[3], E[1]);
    float c = fmaxf(s[2], E[2]);
    float d = fmaxf(s[1], E[3]);
    float e = fmaxf(s[0], E[4]);
    return fminf(fminf(fminf(a, b), fminf(c, d)), fminf(e, s[5]));
}

__device__ __forceinline__ float sum5(const float v[5]) {
    return ((v[0] + v[1]) + (v[2] + v[3])) + v[4];
}
__device__ __forceinline__ float sq5(const float v[5]) {
    return fmaf(v[0], v[0], fmaf(v[1], v[1], fmaf(v[2], v[2], fmaf(v[3], v[3], v[4] * v[4]))));
}

__global__ __launch_bounds__(NTHREADS, 4)
void Net_29291676958726_kernel(const float* __restrict__ x,
                               const float* __restrict__ noise_var,
                               const float* __restrict__ noise_bias,
                               float* __restrict__ out) {
    __shared__ float tile[TILE_H][TILE_STRIDE];

    const int b   = blockIdx.y;
    const int rb  = blockIdx.x * RPB;
    const int tid = threadIdx.y * TX + threadIdx.x;
    const float* __restrict__ xb_ptr = x + (size_t)b * HH * WW;

    // zero-padded tile load: 12 rows x 516 cols, striped over 256 threads
#pragma unroll
    for (int r = 0; r < TILE_H; r++) {
        const int gr = rb - 2 + r;
        const bool rok = (unsigned)gr < HH;
        const float* __restrict__ src = xb_ptr + (size_t)gr * WW;
#pragma unroll
        for (int cc = 0; cc < 3; cc++) {
            int c = tid + cc * NTHREADS;
            if (c < TILE_W) {
                int gc = c - 2;
                tile[r][c] = (rok && (unsigned)gc < WW) ? src[gc] : 0.0f;
            }
        }
    }
    __syncthreads();

    const float nv = noise_var[0];
    const float nb = noise_bias[0];

    const int ty    = threadIdx.y;
    const int xbase = threadIdx.x * PXT;

    // Rotating live state
    float Ecur[5], Enext[5], C3[5];   // sorted columns 2t, 2t+2, 2t+3
    float M[10];                      // merge of columns 2t+1, 2t+2
    float sM, qM, s3, q3;             // sums for M-cols pair and col 2t+3
    float sE0, qE0, sE1, qE1;         // sum/sq queue for E columns (2t, 2t+2)
    float cenE, cenO;

    // ---- prologue: columns 0..3 ----
    {
        float c0[5], c1[5], c2[5], c3v[5];
#pragma unroll
        for (int jp = 0; jp < 2; jp++) {
#pragma unroll
            for (int k = 0; k < 5; k++) {
                float2 gg = *(const float2*)&tile[ty + k][xbase + 2 * jp];
                (jp ? c2 : c0)[k]  = gg.x;
                (jp ? c3v : c1)[k] = gg.y;
            }
        }
        sE0  = sum5(c0);             qE0 = sq5(c0);
        sE1  = sum5(c2);             qE1 = sq5(c2);
        sM   = sum5(c1) + sE1;       qM  = sq5(c1) + qE1;
        s3   = sum5(c3v);            q3  = sq5(c3v);
        cenE = c2[2];
        cenO = c3v[2];
        sort5(c0); sort5(c1); sort5(c2); sort5(c3v);
#pragma unroll
        for (int k = 0; k < 5; k++) { Ecur[k] = c0[k]; Enext[k] = c2[k]; C3[k] = c3v[k]; }
        merge55(c1, c2, M);
    }

    float2* __restrict__ orow =
        (float2*)(out + (size_t)b * HH * WW + (size_t)(rb + ty) * WW + xbase);

#pragma unroll
    for (int t = 0; t < PXT / 2; t++) {
        // fresh columns 2t+4, 2t+5
        float v4[5], v5[5];
#pragma unroll
        for (int k = 0; k < 5; k++) {
            float2 gg = *(const float2*)&tile[ty + k][xbase + 2 * t + 4];
            v4[k] = gg.x;
            v5[k] = gg.y;
        }
        float s4 = sum5(v4), q4 = sq5(v4);
        float s5 = sum5(v5), q5 = sq5(v5);
        float cen4 = v4[2], cen5 = v5[2];
        sort5(v4); sort5(v5);

        float N[10];                   // merge(col 2t+3, col 2t+4) = next M
        merge55(C3, v4, N);

        float s[6];
        prune_mid(M, N, s);

        float sN = s3 + s4;
        float qN = q3 + q4;

        // even pixel p = 2t: window = E(2t) + M-cols + N-cols
        float sum_e = sE0 + sM + sN;
        float sq_e  = qE0 + qM + qN;
        float var_e = fmaxf((sq_e - sum_e * sum_e * 0.04f) * (1.0f / 24.0f), 0.0f);
        float med_e = sel13(s, Ecur);
        float y_e   = cenE - nv * __fdividef(cenE - med_e + nb, var_e + 1e-10f);

        // odd pixel p = 2t+1: window = M-cols + N-cols + col(2t+5)
        float sum_o = sM + sN + s5;
        float sq_o  = qM + qN + q5;
        float var_o = fmaxf((sq_o - sum_o * sum_o * 0.04f) * (1.0f / 24.0f), 0.0f);
        float med_o = sel13(s, v5);
        float y_o   = cenO - nv * __fdividef(cenO - med_o + nb, var_o + 1e-10f);

        orow[t] = make_float2(fmaxf(y_e, 0.0f), fmaxf(y_o, 0.0f));

        // rotate state for pair t+1
#pragma unroll
        for (int k = 0; k < 5; k++) { Ecur[k] = Enext[k]; Enext[k] = v4[k]; C3[k] = v5[k]; }
#pragma unroll
        for (int k = 0; k < 10; k++) M[k] = N[k];
        sM = sN; qM = qN;
        s3 = s5; q3 = q5;
        sE0 = sE1; qE0 = qE1;
        sE1 = s4;  qE1 = q4;
        cenE = cen4; cenO = cen5;
    }
}

extern "C" void kernel_launch(void* const* d_in, const int* in_sizes, int n_in,
                              void* d_out, int out_size) {
    const float* x  = (const float*)d_in[0];
    const float* nv = (const float*)d_in[1];
    const float* nb = (const float*)d_in[2];
    float* out = (float*)d_out;

    dim3 block(TX, RPB);
    dim3 grid(HH / RPB, BATCH);
    Net_29291676958726_kernel<<<grid, block>>>(x, nv, nb, out);
}